// round 2
// baseline (speedup 1.0000x reference)
#include <cuda_runtime.h>
#include <cstdint>

#define N_NODES 10000
#define N_EDGES 65536
#define CIN1    16
#define HID     64

// ---- static device scratch (no allocations allowed) ----
__device__ float g_G[(size_t)N_NODES * 64 * 64];   // per-node edge-weight factor, 164 MB
__device__ float g_h[(size_t)N_EDGES * 64];        // edge-MLP hidden, reused per layer
__device__ float g_XB[N_NODES * 64];               // bias-path per node
__device__ float g_agg[N_NODES * 64];              // scatter accumulator
__device__ float g_y[N_NODES * 64];                // layer-1 output
__device__ float g_z[N_NODES * 64];                // layer-2 output
__device__ float g_deg[N_NODES];                   // in-degree (by dst)

// ---------------------------------------------------------------------------
__global__ void k_zero(int zero_deg) {
    int i = blockIdx.x * blockDim.x + threadIdx.x;
    if (i < N_NODES * 64) g_agg[i] = 0.f;
    if (zero_deg && i < N_NODES) g_deg[i] = 0.f;
}

__global__ void k_deg(const int* __restrict__ ei) {
    int e = blockIdx.x * blockDim.x + threadIdx.x;
    if (e < N_EDGES) atomicAdd(&g_deg[ei[N_EDGES + e]], 1.f);
}

// h[e,j] = relu(b1[j] + sum_k ea[e,k]*w1[k,j]),  ea: [E,4], w1: [4,64]
__global__ void k_edge_hidden(const float* __restrict__ ea,
                              const float* __restrict__ w1,
                              const float* __restrict__ b1) {
    int idx = blockIdx.x * blockDim.x + threadIdx.x;
    if (idx >= N_EDGES * 64) return;
    int e = idx >> 6, j = idx & 63;
    const float* a = ea + (size_t)e * 4;
    float v = b1[j];
#pragma unroll
    for (int k = 0; k < 4; ++k) v = fmaf(a[k], w1[k * 64 + j], v);
    g_h[idx] = fmaxf(v, 0.f);
}

// G[n, m*64+o] = sum_i X[n,i] * w2[m*(CIN*64) + i*64 + o]
// block: 64 nodes x (one m, 64 o).  256 threads, each 4 nodes x 4 o.
template <int CIN>
__global__ void k_gemm_G(const float* __restrict__ X,
                         const float* __restrict__ W2) {
    __shared__ float Xs[64][CIN + 1];
    __shared__ float Ws[CIN * 64];
    const int m  = blockIdx.y;
    const int nb = blockIdx.x * 64;
    const int tid = threadIdx.x;

    const float* wrow = W2 + (size_t)m * (CIN * 64);
    for (int idx = tid; idx < CIN * 64; idx += 256) Ws[idx] = wrow[idx];
    for (int idx = tid; idx < 64 * CIN; idx += 256) {
        int j = idx / CIN, i = idx % CIN;
        int n = nb + j;
        Xs[j][i] = (n < N_NODES) ? X[(size_t)n * CIN + i] : 0.f;
    }
    __syncthreads();

    const int ox = tid & 15;   // o = ox + 16*jo  (conflict-free stride-16)
    const int ny = tid >> 4;   // node = nb + ny*4 + jn
    float acc[4][4];
#pragma unroll
    for (int a = 0; a < 4; ++a)
#pragma unroll
        for (int b = 0; b < 4; ++b) acc[a][b] = 0.f;

    for (int i = 0; i < CIN; ++i) {
        float bv[4], av[4];
#pragma unroll
        for (int jo = 0; jo < 4; ++jo) bv[jo] = Ws[i * 64 + ox + 16 * jo];
#pragma unroll
        for (int jn = 0; jn < 4; ++jn) av[jn] = Xs[ny * 4 + jn][i];
#pragma unroll
        for (int jn = 0; jn < 4; ++jn)
#pragma unroll
            for (int jo = 0; jo < 4; ++jo) acc[jn][jo] = fmaf(av[jn], bv[jo], acc[jn][jo]);
    }
#pragma unroll
    for (int jn = 0; jn < 4; ++jn) {
        int n = nb + ny * 4 + jn;
        if (n < N_NODES) {
            float* gr = g_G + (size_t)n * 4096 + m * 64;
#pragma unroll
            for (int jo = 0; jo < 4; ++jo) gr[ox + 16 * jo] = acc[jn][jo];
        }
    }
}

// XB[n,o] = sum_i X[n,i] * b2[i*64 + o]
template <int CIN>
__global__ void k_xb(const float* __restrict__ X, const float* __restrict__ b2) {
    int idx = blockIdx.x * blockDim.x + threadIdx.x;
    if (idx >= N_NODES * 64) return;
    int n = idx >> 6, o = idx & 63;
    const float* xr = X + (size_t)n * CIN;
    float v = 0.f;
#pragma unroll
    for (int i = 0; i < CIN; ++i) v = fmaf(xr[i], b2[i * 64 + o], v);
    g_XB[idx] = v;
}

// one warp per edge: msg = h[e] @ G[src] + XB[src]; atomicAdd into agg[dst]
__global__ void k_edge_msg(const int* __restrict__ ei) {
    int warpId = (blockIdx.x * blockDim.x + threadIdx.x) >> 5;
    int lane   = threadIdx.x & 31;
    if (warpId >= N_EDGES) return;
    const int src = ei[warpId];
    const int dst = ei[N_EDGES + warpId];

    const float* h = g_h + (size_t)warpId * 64;
    const float  h0 = h[lane];
    const float  h1 = h[lane + 32];
    const float* g  = g_G + (size_t)src * 4096;

    float acc0 = g_XB[src * 64 + lane];
    float acc1 = g_XB[src * 64 + 32 + lane];

    const unsigned FULL = 0xffffffffu;
#pragma unroll
    for (int m = 0; m < 32; ++m) {
        float hm = __shfl_sync(FULL, h0, m);
        acc0 = fmaf(hm, g[m * 64 + lane], acc0);
        acc1 = fmaf(hm, g[m * 64 + 32 + lane], acc1);
    }
#pragma unroll
    for (int m = 0; m < 32; ++m) {
        float hm = __shfl_sync(FULL, h1, m);
        acc0 = fmaf(hm, g[(m + 32) * 64 + lane], acc0);
        acc1 = fmaf(hm, g[(m + 32) * 64 + 32 + lane], acc1);
    }
    atomicAdd(&g_agg[dst * 64 + lane], acc0);
    atomicAdd(&g_agg[dst * 64 + 32 + lane], acc1);
}

// out[n,o] = relu(agg/max(deg,1) + x@root + bias)
template <int CIN>
__global__ void k_finalize(const float* __restrict__ Xin,
                           const float* __restrict__ root,
                           const float* __restrict__ bias,
                           float* __restrict__ out) {
    int idx = blockIdx.x * blockDim.x + threadIdx.x;
    if (idx >= N_NODES * 64) return;
    int n = idx >> 6, o = idx & 63;
    float inv = 1.f / fmaxf(g_deg[n], 1.f);
    float v = g_agg[idx] * inv + bias[o];
    const float* xr = Xin + (size_t)n * CIN;
#pragma unroll 8
    for (int i = 0; i < CIN; ++i) v = fmaf(xr[i], root[i * 64 + o], v);
    out[idx] = fmaxf(v, 0.f);
}

// readout: warp per node.  t = relu(z@lin1+b1) [8]; out = t@lin2 + b2
__global__ void k_readout(const float* __restrict__ w1, const float* __restrict__ b1,
                          const float* __restrict__ w2, const float* __restrict__ b2,
                          float* __restrict__ out) {
    int warp = (blockIdx.x * blockDim.x + threadIdx.x) >> 5;
    int lane = threadIdx.x & 31;
    if (warp >= N_NODES) return;
    const float* zr = g_z + (size_t)warp * 64;
    float z0 = zr[lane], z1 = zr[lane + 32];
    float p[8];
#pragma unroll
    for (int j = 0; j < 8; ++j)
        p[j] = z0 * w1[lane * 8 + j] + z1 * w1[(lane + 32) * 8 + j];
    const unsigned FULL = 0xffffffffu;
#pragma unroll
    for (int off = 16; off; off >>= 1)
#pragma unroll
        for (int j = 0; j < 8; ++j) p[j] += __shfl_down_sync(FULL, p[j], off);
    if (lane == 0) {
        float r = b2[0];
#pragma unroll
        for (int j = 0; j < 8; ++j) r += fmaxf(p[j] + b1[j], 0.f) * w2[j];
        out[warp] = r;
    }
}

// ---------------------------------------------------------------------------
extern "C" void kernel_launch(void* const* d_in, const int* in_sizes, int n_in,
                              void* d_out, int out_size) {
    const float* x      = (const float*)d_in[0];
    const int*   ei     = (const int*)d_in[1];     // int32! jax x64 disabled
    const float* ea     = (const float*)d_in[2];
    const float* nn1_w1 = (const float*)d_in[3];
    const float* nn1_b1 = (const float*)d_in[4];
    const float* nn1_w2 = (const float*)d_in[5];
    const float* nn1_b2 = (const float*)d_in[6];
    const float* root1  = (const float*)d_in[7];
    const float* bias1  = (const float*)d_in[8];
    const float* nn2_w1 = (const float*)d_in[9];
    const float* nn2_b1 = (const float*)d_in[10];
    const float* nn2_w2 = (const float*)d_in[11];
    const float* nn2_b2 = (const float*)d_in[12];
    const float* root2  = (const float*)d_in[13];
    const float* bias2  = (const float*)d_in[14];
    const float* lin1_w = (const float*)d_in[15];
    const float* lin1_b = (const float*)d_in[16];
    const float* lin2_w = (const float*)d_in[17];
    const float* lin2_b = (const float*)d_in[18];
    float* out = (float*)d_out;

    float* d_y = nullptr; float* d_z = nullptr;
    cudaGetSymbolAddress((void**)&d_y, g_y);
    cudaGetSymbolAddress((void**)&d_z, g_z);

    const int T = 256;
    const int bNO   = (N_NODES * 64 + T - 1) / T;   // node x 64 grids
    const int bEH   = (N_EDGES * 64 + T - 1) / T;   // edge hidden
    const int bMSG  = (N_EDGES * 32 + T - 1) / T;   // warp per edge
    const int bRD   = (N_NODES * 32 + T - 1) / T;   // warp per node
    dim3 gG((N_NODES + 63) / 64, 64);

    // ---- layer 1 (cin = 16) ----
    k_zero<<<bNO, T>>>(1);
    k_deg<<<(N_EDGES + T - 1) / T, T>>>(ei);
    k_edge_hidden<<<bEH, T>>>(ea, nn1_w1, nn1_b1);
    k_gemm_G<CIN1><<<gG, T>>>(x, nn1_w2);
    k_xb<CIN1><<<bNO, T>>>(x, nn1_b2);
    k_edge_msg<<<bMSG, T>>>(ei);
    k_finalize<CIN1><<<bNO, T>>>(x, root1, bias1, d_y);

    // ---- layer 2 (cin = 64) ----
    k_zero<<<bNO, T>>>(0);
    k_edge_hidden<<<bEH, T>>>(ea, nn2_w1, nn2_b1);
    k_gemm_G<HID><<<gG, T>>>(d_y, nn2_w2);
    k_xb<HID><<<bNO, T>>>(d_y, nn2_b2);
    k_edge_msg<<<bMSG, T>>>(ei);
    k_finalize<HID><<<bNO, T>>>(d_y, root2, bias2, d_z);

    // ---- readout ----
    k_readout<<<bRD, T>>>(lin1_w, lin1_b, lin2_w, lin2_b, out);
}

// round 4
// speedup vs baseline: 1.0316x; 1.0316x over previous
#include <cuda_runtime.h>
#include <cstdint>

#define N_NODES 10000
#define N_EDGES 65536
#define CIN1    16
#define HID     64

// ---- static device scratch (no allocations allowed) ----
__device__ float g_G[(size_t)N_NODES * 64 * 64];   // per-node edge-weight factor, 164 MB
__device__ float g_h[(size_t)N_EDGES * 64];        // edge-MLP hidden
__device__ float g_XB[N_NODES * 64];               // bias-path per node
__device__ float g_agg[N_NODES * 64];              // scatter accumulator
__device__ float g_y[N_NODES * 64];                // layer-1 output
__device__ float g_z[N_NODES * 64];                // layer-2 output
__device__ float g_deg[N_NODES];                   // in-degree (by dst)

// ---- edge sort-by-src scratch ----
__device__ int g_cnt[N_NODES];
__device__ int g_off[N_NODES];
__device__ int g_cur[N_NODES];
__device__ int g_se[N_EDGES];                      // sorted edge id
__device__ int g_ss[N_EDGES];                      // sorted src
__device__ int g_sd[N_EDGES];                      // sorted dst

// ---------------------------------------------------------------------------
__global__ void k_init() {
    int i = blockIdx.x * blockDim.x + threadIdx.x;
    if (i < N_NODES * 64) g_agg[i] = 0.f;
    if (i < N_NODES) { g_deg[i] = 0.f; g_cnt[i] = 0; g_cur[i] = 0; }
}

__global__ void k_zero_agg() {
    int i = blockIdx.x * blockDim.x + threadIdx.x;
    if (i < N_NODES * 64) g_agg[i] = 0.f;
}

// histogram src counts + dst degrees in one pass
__global__ void k_hist(const int* __restrict__ ei) {
    int e = blockIdx.x * blockDim.x + threadIdx.x;
    if (e >= N_EDGES) return;
    atomicAdd(&g_cnt[ei[e]], 1);
    atomicAdd(&g_deg[ei[N_EDGES + e]], 1.f);
}

// exclusive prefix sum over g_cnt -> g_off (single block, 1024 threads)
__global__ void k_scan() {
    __shared__ int s[1024];
    __shared__ int carry;
    int tid = threadIdx.x;
    if (tid == 0) carry = 0;
    __syncthreads();
    for (int base = 0; base < N_NODES; base += 1024) {
        int i = base + tid;
        int v = (i < N_NODES) ? g_cnt[i] : 0;
        s[tid] = v;
        __syncthreads();
        for (int d = 1; d < 1024; d <<= 1) {
            int t = (tid >= d) ? s[tid - d] : 0;
            __syncthreads();
            s[tid] += t;
            __syncthreads();
        }
        if (i < N_NODES) g_off[i] = s[tid] - v + carry;
        __syncthreads();
        if (tid == 0) carry += s[1023];
        __syncthreads();
    }
}

__global__ void k_scatter(const int* __restrict__ ei) {
    int e = blockIdx.x * blockDim.x + threadIdx.x;
    if (e >= N_EDGES) return;
    int src = ei[e];
    int dst = ei[N_EDGES + e];
    int pos = g_off[src] + atomicAdd(&g_cur[src], 1);
    g_se[pos] = e;
    g_ss[pos] = src;
    g_sd[pos] = dst;
}

// h[e,j] = relu(b1[j] + sum_k ea[e,k]*w1[k,j])
__global__ void k_edge_hidden(const float* __restrict__ ea,
                              const float* __restrict__ w1,
                              const float* __restrict__ b1) {
    int idx = blockIdx.x * blockDim.x + threadIdx.x;
    if (idx >= N_EDGES * 64) return;
    int e = idx >> 6, j = idx & 63;
    const float* a = ea + (size_t)e * 4;
    float v = b1[j];
#pragma unroll
    for (int k = 0; k < 4; ++k) v = fmaf(a[k], w1[k * 64 + j], v);
    g_h[idx] = fmaxf(v, 0.f);
}

// G[n, m*64+o] = sum_i X[n,i] * w2[m*(CIN*64) + i*64 + o]
template <int CIN>
__global__ void k_gemm_G(const float* __restrict__ X,
                         const float* __restrict__ W2) {
    __shared__ float Xs[64][CIN + 1];
    __shared__ float Ws[CIN * 64];
    const int m  = blockIdx.y;
    const int nb = blockIdx.x * 64;
    const int tid = threadIdx.x;

    const float* wrow = W2 + (size_t)m * (CIN * 64);
    for (int idx = tid; idx < CIN * 64; idx += 256) Ws[idx] = wrow[idx];
    for (int idx = tid; idx < 64 * CIN; idx += 256) {
        int j = idx / CIN, i = idx % CIN;
        int n = nb + j;
        Xs[j][i] = (n < N_NODES) ? X[(size_t)n * CIN + i] : 0.f;
    }
    __syncthreads();

    const int ox = tid & 15;
    const int ny = tid >> 4;
    float acc[4][4];
#pragma unroll
    for (int a = 0; a < 4; ++a)
#pragma unroll
        for (int b = 0; b < 4; ++b) acc[a][b] = 0.f;

    for (int i = 0; i < CIN; ++i) {
        float bv[4], av[4];
#pragma unroll
        for (int jo = 0; jo < 4; ++jo) bv[jo] = Ws[i * 64 + ox + 16 * jo];
#pragma unroll
        for (int jn = 0; jn < 4; ++jn) av[jn] = Xs[ny * 4 + jn][i];
#pragma unroll
        for (int jn = 0; jn < 4; ++jn)
#pragma unroll
            for (int jo = 0; jo < 4; ++jo) acc[jn][jo] = fmaf(av[jn], bv[jo], acc[jn][jo]);
    }
#pragma unroll
    for (int jn = 0; jn < 4; ++jn) {
        int n = nb + ny * 4 + jn;
        if (n < N_NODES) {
            float* gr = g_G + (size_t)n * 4096 + m * 64;
#pragma unroll
            for (int jo = 0; jo < 4; ++jo) gr[ox + 16 * jo] = acc[jn][jo];
        }
    }
}

// XB[n,o] = sum_i X[n,i] * b2[i*64 + o]
template <int CIN>
__global__ void k_xb(const float* __restrict__ X, const float* __restrict__ b2) {
    int idx = blockIdx.x * blockDim.x + threadIdx.x;
    if (idx >= N_NODES * 64) return;
    int n = idx >> 6, o = idx & 63;
    const float* xr = X + (size_t)n * CIN;
    float v = 0.f;
#pragma unroll
    for (int i = 0; i < CIN; ++i) v = fmaf(xr[i], b2[i * 64 + o], v);
    g_XB[idx] = v;
}

// one warp per SORTED edge: msg = h[e] @ G[src] + XB[src]; atomicAdd agg[dst]
__global__ void k_edge_msg() {
    int p    = (blockIdx.x * blockDim.x + threadIdx.x) >> 5;
    int lane = threadIdx.x & 31;
    if (p >= N_EDGES) return;
    const int e   = g_se[p];
    const int src = g_ss[p];
    const int dst = g_sd[p];

    const float* h = g_h + (size_t)e * 64;
    const float  h0 = h[lane];
    const float  h1 = h[lane + 32];
    const float* g  = g_G + (size_t)src * 4096;

    float acc0 = g_XB[src * 64 + lane];
    float acc1 = g_XB[src * 64 + 32 + lane];

    const unsigned FULL = 0xffffffffu;
#pragma unroll
    for (int m = 0; m < 32; ++m) {
        float hm = __shfl_sync(FULL, h0, m);
        acc0 = fmaf(hm, g[m * 64 + lane], acc0);
        acc1 = fmaf(hm, g[m * 64 + 32 + lane], acc1);
    }
#pragma unroll
    for (int m = 0; m < 32; ++m) {
        float hm = __shfl_sync(FULL, h1, m);
        acc0 = fmaf(hm, g[(m + 32) * 64 + lane], acc0);
        acc1 = fmaf(hm, g[(m + 32) * 64 + 32 + lane], acc1);
    }
    atomicAdd(&g_agg[dst * 64 + lane], acc0);
    atomicAdd(&g_agg[dst * 64 + 32 + lane], acc1);
}

// out[n,o] = relu(agg/max(deg,1) + x@root + bias)
template <int CIN>
__global__ void k_finalize(const float* __restrict__ Xin,
                           const float* __restrict__ root,
                           const float* __restrict__ bias,
                           float* __restrict__ out) {
    int idx = blockIdx.x * blockDim.x + threadIdx.x;
    if (idx >= N_NODES * 64) return;
    int n = idx >> 6, o = idx & 63;
    float inv = 1.f / fmaxf(g_deg[n], 1.f);
    float v = g_agg[idx] * inv + bias[o];
    const float* xr = Xin + (size_t)n * CIN;
#pragma unroll 8
    for (int i = 0; i < CIN; ++i) v = fmaf(xr[i], root[i * 64 + o], v);
    out[idx] = fmaxf(v, 0.f);
}

// readout: warp per node
__global__ void k_readout(const float* __restrict__ w1, const float* __restrict__ b1,
                          const float* __restrict__ w2, const float* __restrict__ b2,
                          float* __restrict__ out) {
    int warp = (blockIdx.x * blockDim.x + threadIdx.x) >> 5;
    int lane = threadIdx.x & 31;
    if (warp >= N_NODES) return;
    const float* zr = g_z + (size_t)warp * 64;
    float z0 = zr[lane], z1 = zr[lane + 32];
    float p[8];
#pragma unroll
    for (int j = 0; j < 8; ++j)
        p[j] = z0 * w1[lane * 8 + j] + z1 * w1[(lane + 32) * 8 + j];
    const unsigned FULL = 0xffffffffu;
#pragma unroll
    for (int off = 16; off; off >>= 1)
#pragma unroll
        for (int j = 0; j < 8; ++j) p[j] += __shfl_down_sync(FULL, p[j], off);
    if (lane == 0) {
        float r = b2[0];
#pragma unroll
        for (int j = 0; j < 8; ++j) r += fmaxf(p[j] + b1[j], 0.f) * w2[j];
        out[warp] = r;
    }
}

// ---------------------------------------------------------------------------
extern "C" void kernel_launch(void* const* d_in, const int* in_sizes, int n_in,
                              void* d_out, int out_size) {
    const float* x      = (const float*)d_in[0];
    const int*   ei     = (const int*)d_in[1];     // int32 (jax x64 disabled)
    const float* ea     = (const float*)d_in[2];
    const float* nn1_w1 = (const float*)d_in[3];
    const float* nn1_b1 = (const float*)d_in[4];
    const float* nn1_w2 = (const float*)d_in[5];
    const float* nn1_b2 = (const float*)d_in[6];
    const float* root1  = (const float*)d_in[7];
    const float* bias1  = (const float*)d_in[8];
    const float* nn2_w1 = (const float*)d_in[9];
    const float* nn2_b1 = (const float*)d_in[10];
    const float* nn2_w2 = (const float*)d_in[11];
    const float* nn2_b2 = (const float*)d_in[12];
    const float* root2  = (const float*)d_in[13];
    const float* bias2  = (const float*)d_in[14];
    const float* lin1_w = (const float*)d_in[15];
    const float* lin1_b = (const float*)d_in[16];
    const float* lin2_w = (const float*)d_in[17];
    const float* lin2_b = (const float*)d_in[18];
    float* out = (float*)d_out;

    float* d_y = nullptr; float* d_z = nullptr;
    cudaGetSymbolAddress((void**)&d_y, g_y);
    cudaGetSymbolAddress((void**)&d_z, g_z);

    const int T = 256;
    const int bNO  = (N_NODES * 64 + T - 1) / T;
    const int bE   = (N_EDGES + T - 1) / T;
    const int bEH  = (N_EDGES * 64 + T - 1) / T;
    const int bMSG = (N_EDGES * 32 + T - 1) / T;
    const int bRD  = (N_NODES * 32 + T - 1) / T;
    dim3 gG((N_NODES + 63) / 64, 64);

    // ---- sort edges by src (+ histograms) ----
    k_init<<<bNO, T>>>();
    k_hist<<<bE, T>>>(ei);
    k_scan<<<1, 1024>>>();
    k_scatter<<<bE, T>>>(ei);

    // ---- layer 1 (cin = 16) ----
    k_edge_hidden<<<bEH, T>>>(ea, nn1_w1, nn1_b1);
    k_gemm_G<CIN1><<<gG, T>>>(x, nn1_w2);
    k_xb<CIN1><<<bNO, T>>>(x, nn1_b2);
    k_edge_msg<<<bMSG, T>>>();
    k_finalize<CIN1><<<bNO, T>>>(x, root1, bias1, d_y);

    // ---- layer 2 (cin = 64) ----
    k_zero_agg<<<bNO, T>>>();
    k_edge_hidden<<<bEH, T>>>(ea, nn2_w1, nn2_b1);
    k_gemm_G<HID><<<gG, T>>>(d_y, nn2_w2);
    k_xb<HID><<<bNO, T>>>(d_y, nn2_b2);
    k_edge_msg<<<bMSG, T>>>();
    k_finalize<HID><<<bNO, T>>>(d_y, root2, bias2, d_z);

    // ---- readout ----
    k_readout<<<bRD, T>>>(lin1_w, lin1_b, lin2_w, lin2_b, out);
}

// round 5
// speedup vs baseline: 1.0926x; 1.0592x over previous
#include <cuda_runtime.h>
#include <cuda_fp16.h>
#include <mma.h>
#include <cstdint>

using namespace nvcuda;

#define N_NODES 10000
#define N_PAD   10048          // 157 * 64
#define N_EDGES 65536
#define CIN1    16
#define HID     64

// ---- static device scratch (no allocations allowed) ----
__device__ float  g_G[(size_t)N_PAD * 4096];       // per-node factor, fp32, 165 MB
__device__ __half g_Xh[N_PAD * 64];                // fp16 split of node features
__device__ __half g_Xl[N_PAD * 64];
__device__ __half g_Bh[64 * 4096];                 // fp16 split of permuted W2
__device__ __half g_Bl[64 * 4096];
__device__ float  g_h[(size_t)N_EDGES * 64];       // edge-MLP hidden
__device__ float  g_XB[N_NODES * 64];              // bias-path per node
__device__ float  g_agg[N_NODES * 64];             // scatter accumulator
__device__ float  g_y[N_NODES * 64];               // layer-1 output
__device__ float  g_z[N_NODES * 64];               // layer-2 output
__device__ float  g_deg[N_NODES];                  // in-degree (by dst)

// ---- edge sort-by-src scratch ----
__device__ int g_cnt[N_NODES];
__device__ int g_off[N_NODES];
__device__ int g_cur[N_NODES];
__device__ int g_se[N_EDGES];
__device__ int g_ss[N_EDGES];
__device__ int g_sd[N_EDGES];

// ---------------------------------------------------------------------------
__global__ void k_init() {
    int i = blockIdx.x * blockDim.x + threadIdx.x;
    if (i < N_NODES * 64) g_agg[i] = 0.f;
    if (i < N_NODES) { g_deg[i] = 0.f; g_cnt[i] = 0; g_cur[i] = 0; }
}

__global__ void k_zero_agg() {
    int i = blockIdx.x * blockDim.x + threadIdx.x;
    if (i < N_NODES * 64) g_agg[i] = 0.f;
}

__global__ void k_hist(const int* __restrict__ ei) {
    int e = blockIdx.x * blockDim.x + threadIdx.x;
    if (e >= N_EDGES) return;
    atomicAdd(&g_cnt[ei[e]], 1);
    atomicAdd(&g_deg[ei[N_EDGES + e]], 1.f);
}

__global__ void k_scan() {
    __shared__ int s[1024];
    __shared__ int carry;
    int tid = threadIdx.x;
    if (tid == 0) carry = 0;
    __syncthreads();
    for (int base = 0; base < N_NODES; base += 1024) {
        int i = base + tid;
        int v = (i < N_NODES) ? g_cnt[i] : 0;
        s[tid] = v;
        __syncthreads();
        for (int d = 1; d < 1024; d <<= 1) {
            int t = (tid >= d) ? s[tid - d] : 0;
            __syncthreads();
            s[tid] += t;
            __syncthreads();
        }
        if (i < N_NODES) g_off[i] = s[tid] - v + carry;
        __syncthreads();
        if (tid == 0) carry += s[1023];
        __syncthreads();
    }
}

__global__ void k_scatter(const int* __restrict__ ei) {
    int e = blockIdx.x * blockDim.x + threadIdx.x;
    if (e >= N_EDGES) return;
    int src = ei[e];
    int dst = ei[N_EDGES + e];
    int pos = g_off[src] + atomicAdd(&g_cur[src], 1);
    g_se[pos] = e;
    g_ss[pos] = src;
    g_sd[pos] = dst;
}

// ---- fp16 split conversions ------------------------------------------------
// X [N, CIN] fp32 -> Xh/Xl [N_PAD, CIN] fp16 (zero-padded tail rows)
template <int CIN>
__global__ void k_conv_X(const float* __restrict__ X) {
    int idx = blockIdx.x * blockDim.x + threadIdx.x;
    if (idx >= N_PAD * CIN) return;
    int n = idx / CIN;
    float v = (n < N_NODES) ? X[idx] : 0.f;
    __half h = __float2half(v);
    g_Xh[idx] = h;
    g_Xl[idx] = __float2half(v - __half2float(h));
}

// W2 [64, CIN*64] -> B [CIN, 4096] permuted: B[i, m*64+o] = W2[m, i*64+o]
template <int CIN>
__global__ void k_conv_B(const float* __restrict__ W2) {
    int idx = blockIdx.x * blockDim.x + threadIdx.x;
    if (idx >= CIN * 4096) return;
    int i = idx >> 12;
    int c = idx & 4095;
    int m = c >> 6, o = c & 63;
    float v = W2[(size_t)m * (CIN * 64) + i * 64 + o];
    __half h = __float2half(v);
    g_Bh[idx] = h;
    g_Bl[idx] = __float2half(v - __half2float(h));
}

// h[e,j] = relu(b1[j] + sum_k ea[e,k]*w1[k,j])
__global__ void k_edge_hidden(const float* __restrict__ ea,
                              const float* __restrict__ w1,
                              const float* __restrict__ b1) {
    int idx = blockIdx.x * blockDim.x + threadIdx.x;
    if (idx >= N_EDGES * 64) return;
    int e = idx >> 6, j = idx & 63;
    const float* a = ea + (size_t)e * 4;
    float v = b1[j];
#pragma unroll
    for (int k = 0; k < 4; ++k) v = fmaf(a[k], w1[k * 64 + j], v);
    g_h[idx] = fmaxf(v, 0.f);
}

// ---- G = X @ B via HMMA, 2-term fp16 split, fp32 accum/store --------------
// grid (N_PAD/64, 4096/64), block 128 (4 warps). Warp w: rows [bx*64+w*16, +16),
// cols [by*64, +64) as 4 16x16 tiles.
template <int K>
__global__ void k_gemm_wmma() {
    const int w    = threadIdx.x >> 5;
    const int row0 = blockIdx.x * 64 + w * 16;
    const int col0 = blockIdx.y * 64;

    wmma::fragment<wmma::accumulator, 16, 16, 16, float> acc[4];
#pragma unroll
    for (int t = 0; t < 4; ++t) wmma::fill_fragment(acc[t], 0.f);

#pragma unroll
    for (int k = 0; k < K; k += 16) {
        wmma::fragment<wmma::matrix_a, 16, 16, 16, __half, wmma::row_major> ah, al;
        wmma::load_matrix_sync(ah, g_Xh + (size_t)row0 * K + k, K);
        wmma::load_matrix_sync(al, g_Xl + (size_t)row0 * K + k, K);
#pragma unroll
        for (int t = 0; t < 4; ++t) {
            wmma::fragment<wmma::matrix_b, 16, 16, 16, __half, wmma::row_major> bh, bl;
            wmma::load_matrix_sync(bh, g_Bh + (size_t)k * 4096 + col0 + t * 16, 4096);
            wmma::load_matrix_sync(bl, g_Bl + (size_t)k * 4096 + col0 + t * 16, 4096);
            wmma::mma_sync(acc[t], ah, bh, acc[t]);
            wmma::mma_sync(acc[t], ah, bl, acc[t]);
            wmma::mma_sync(acc[t], al, bh, acc[t]);
        }
    }
#pragma unroll
    for (int t = 0; t < 4; ++t)
        wmma::store_matrix_sync(g_G + (size_t)row0 * 4096 + col0 + t * 16,
                                acc[t], 4096, wmma::mem_row_major);
}

// XB[n,o] = sum_i X[n,i] * b2[i*64 + o]
template <int CIN>
__global__ void k_xb(const float* __restrict__ X, const float* __restrict__ b2) {
    int idx = blockIdx.x * blockDim.x + threadIdx.x;
    if (idx >= N_NODES * 64) return;
    int n = idx >> 6, o = idx & 63;
    const float* xr = X + (size_t)n * CIN;
    float v = 0.f;
#pragma unroll
    for (int i = 0; i < CIN; ++i) v = fmaf(xr[i], b2[i * 64 + o], v);
    g_XB[idx] = v;
}

// one warp per SORTED edge: msg = h[e] @ G[src] + XB[src]; atomicAdd agg[dst]
// lane handles outputs o = 2*lane, 2*lane+1 (float2 loads from G).
__global__ void k_edge_msg() {
    int p    = (blockIdx.x * blockDim.x + threadIdx.x) >> 5;
    int lane = threadIdx.x & 31;
    if (p >= N_EDGES) return;
    const int e   = g_se[p];
    const int src = g_ss[p];
    const int dst = g_sd[p];

    const float* h = g_h + (size_t)e * 64;
    const float  h0 = h[lane];
    const float  h1 = h[lane + 32];
    const float* g  = g_G + (size_t)src * 4096;

    float2 acc = *(const float2*)&g_XB[src * 64 + 2 * lane];

    const unsigned FULL = 0xffffffffu;
#pragma unroll
    for (int m = 0; m < 32; ++m) {
        float hm = __shfl_sync(FULL, h0, m);
        float2 gv = *(const float2*)&g[m * 64 + 2 * lane];
        acc.x = fmaf(hm, gv.x, acc.x);
        acc.y = fmaf(hm, gv.y, acc.y);
    }
#pragma unroll
    for (int m = 0; m < 32; ++m) {
        float hm = __shfl_sync(FULL, h1, m);
        float2 gv = *(const float2*)&g[(m + 32) * 64 + 2 * lane];
        acc.x = fmaf(hm, gv.x, acc.x);
        acc.y = fmaf(hm, gv.y, acc.y);
    }
    atomicAdd(&g_agg[dst * 64 + 2 * lane], acc.x);
    atomicAdd(&g_agg[dst * 64 + 2 * lane + 1], acc.y);
}

// out[n,o] = relu(agg/max(deg,1) + x@root + bias)
template <int CIN>
__global__ void k_finalize(const float* __restrict__ Xin,
                           const float* __restrict__ root,
                           const float* __restrict__ bias,
                           float* __restrict__ out) {
    int idx = blockIdx.x * blockDim.x + threadIdx.x;
    if (idx >= N_NODES * 64) return;
    int n = idx >> 6, o = idx & 63;
    float inv = 1.f / fmaxf(g_deg[n], 1.f);
    float v = g_agg[idx] * inv + bias[o];
    const float* xr = Xin + (size_t)n * CIN;
#pragma unroll 8
    for (int i = 0; i < CIN; ++i) v = fmaf(xr[i], root[i * 64 + o], v);
    out[idx] = fmaxf(v, 0.f);
}

// readout: warp per node
__global__ void k_readout(const float* __restrict__ w1, const float* __restrict__ b1,
                          const float* __restrict__ w2, const float* __restrict__ b2,
                          float* __restrict__ out) {
    int warp = (blockIdx.x * blockDim.x + threadIdx.x) >> 5;
    int lane = threadIdx.x & 31;
    if (warp >= N_NODES) return;
    const float* zr = g_z + (size_t)warp * 64;
    float z0 = zr[lane], z1 = zr[lane + 32];
    float p[8];
#pragma unroll
    for (int j = 0; j < 8; ++j)
        p[j] = z0 * w1[lane * 8 + j] + z1 * w1[(lane + 32) * 8 + j];
    const unsigned FULL = 0xffffffffu;
#pragma unroll
    for (int off = 16; off; off >>= 1)
#pragma unroll
        for (int j = 0; j < 8; ++j) p[j] += __shfl_down_sync(FULL, p[j], off);
    if (lane == 0) {
        float r = b2[0];
#pragma unroll
        for (int j = 0; j < 8; ++j) r += fmaxf(p[j] + b1[j], 0.f) * w2[j];
        out[warp] = r;
    }
}

// ---------------------------------------------------------------------------
extern "C" void kernel_launch(void* const* d_in, const int* in_sizes, int n_in,
                              void* d_out, int out_size) {
    const float* x      = (const float*)d_in[0];
    const int*   ei     = (const int*)d_in[1];     // int32 (jax x64 disabled)
    const float* ea     = (const float*)d_in[2];
    const float* nn1_w1 = (const float*)d_in[3];
    const float* nn1_b1 = (const float*)d_in[4];
    const float* nn1_w2 = (const float*)d_in[5];
    const float* nn1_b2 = (const float*)d_in[6];
    const float* root1  = (const float*)d_in[7];
    const float* bias1  = (const float*)d_in[8];
    const float* nn2_w1 = (const float*)d_in[9];
    const float* nn2_b1 = (const float*)d_in[10];
    const float* nn2_w2 = (const float*)d_in[11];
    const float* nn2_b2 = (const float*)d_in[12];
    const float* root2  = (const float*)d_in[13];
    const float* bias2  = (const float*)d_in[14];
    const float* lin1_w = (const float*)d_in[15];
    const float* lin1_b = (const float*)d_in[16];
    const float* lin2_w = (const float*)d_in[17];
    const float* lin2_b = (const float*)d_in[18];
    float* out = (float*)d_out;

    float* d_y = nullptr; float* d_z = nullptr;
    cudaGetSymbolAddress((void**)&d_y, g_y);
    cudaGetSymbolAddress((void**)&d_z, g_z);

    const int T = 256;
    const int bNO  = (N_NODES * 64 + T - 1) / T;
    const int bE   = (N_EDGES + T - 1) / T;
    const int bEH  = (N_EDGES * 64 + T - 1) / T;
    const int bMSG = (N_EDGES * 32 + T - 1) / T;
    const int bRD  = (N_NODES * 32 + T - 1) / T;
    dim3 gW(N_PAD / 64, 64);   // wmma grid

    // ---- sort edges by src (+ histograms) ----
    k_init<<<bNO, T>>>();
    k_hist<<<bE, T>>>(ei);
    k_scan<<<1, 1024>>>();
    k_scatter<<<bE, T>>>(ei);

    // ---- layer 1 (cin = 16) ----
    k_conv_B<CIN1><<<(CIN1 * 4096 + T - 1) / T, T>>>(nn1_w2);
    k_conv_X<CIN1><<<(N_PAD * CIN1 + T - 1) / T, T>>>(x);
    k_edge_hidden<<<bEH, T>>>(ea, nn1_w1, nn1_b1);
    k_gemm_wmma<CIN1><<<gW, 128>>>();
    k_xb<CIN1><<<bNO, T>>>(x, nn1_b2);
    k_edge_msg<<<bMSG, T>>>();
    k_finalize<CIN1><<<bNO, T>>>(x, root1, bias1, d_y);

    // ---- layer 2 (cin = 64) ----
    k_zero_agg<<<bNO, T>>>();
    k_conv_B<HID><<<(HID * 4096 + T - 1) / T, T>>>(nn2_w2);
    k_conv_X<HID><<<(N_PAD * HID + T - 1) / T, T>>>(d_y);
    k_edge_hidden<<<bEH, T>>>(ea, nn2_w1, nn2_b1);
    k_gemm_wmma<HID><<<gW, 128>>>();
    k_xb<HID><<<bNO, T>>>(d_y, nn2_b2);
    k_edge_msg<<<bMSG, T>>>();
    k_finalize<HID><<<bNO, T>>>(d_y, root2, bias2, d_z);

    // ---- readout ----
    k_readout<<<bRD, T>>>(lin1_w, lin1_b, lin2_w, lin2_b, out);
}